// round 8
// baseline (speedup 1.0000x reference)
#include <cuda_runtime.h>
#include <math.h>

// Problem: B=128, OUT=1024, IN=1024
// d_in: 0=input(128*1024) 1=weight(1024*1024) 2=bias(1024) 3=x0 4=dx 5=a 6=d
// out: (128,1024) float32
//
// res collapses exactly to Yb + bias (bit-exact vs JAX partitionable
// threefry; rel_err == 0.0 measured in R3/R5).
//
// R6: pipe rebalance. alu pipe was 95.4% binding, fma 27.7% idle.
//  - all threefry adds -> IMAD via mad.lo.u32 with MEMORY-opaque `one`
//    (R4's mov-immediate opacity was const-folded by ptxas).
//  - 4 of 20 rotates -> fma pipe: rot(x,r) = mul.lo(x,2^r)|mul.hi(x,2^r),
//    multiplier opaque; OR folds into the round XOR as one LOP3.
//  - y>>9 -> mul.hi(y, 2^23) (opaque 2^23).

#define B_DIM   128
#define OUT_DIM 1024
#define IN_DIM  1024

// Batch-independent synapse gain, pre-scaled: s23 = 2^23 * (d + a*sigmoid(dx*(w-x0))).
__device__ float g_s23[OUT_DIM * IN_DIM];
// Runtime-written opacity constants: {1, 1<<13, 1<<17, 1<<23}.
__device__ unsigned int g_rc[4];

__global__ void prep_kernel(const float* __restrict__ w,
                            const float* __restrict__ x0,
                            const float* __restrict__ dx,
                            const float* __restrict__ a,
                            const float* __restrict__ d) {
    int idx = blockIdx.x * blockDim.x + threadIdx.x;  // exactly 1M threads
    if (idx == 0) {
        g_rc[0] = 1u;
        g_rc[1] = 1u << 13;
        g_rc[2] = 1u << 17;
        g_rc[3] = 1u << 23;
    }
    float z = dx[idx] * (w[idx] - x0[idx]);
    float e = expf(-fabsf(z));
    float t = 1.0f / (1.0f + e);
    float sig = (z >= 0.0f) ? t : e * t;
    g_s23[idx] = (d[idx] + a[idx] * sig) * 8388608.0f;  // * 2^23, exact scale
}

// a + b on the fma pipe: IMAD(a, one, b); `one` is memory-opaque.
__device__ __forceinline__ unsigned int madd(unsigned int a, unsigned int b,
                                             unsigned int one) {
    unsigned int r;
    asm("mad.lo.u32 %0, %1, %2, %3;" : "=r"(r) : "r"(a), "r"(one), "r"(b));
    return r;
}
__device__ __forceinline__ unsigned int mullo(unsigned int a, unsigned int m) {
    unsigned int r;
    asm("mul.lo.u32 %0, %1, %2;" : "=r"(r) : "r"(a), "r"(m));
    return r;
}
__device__ __forceinline__ unsigned int mulhi_(unsigned int a, unsigned int m) {
    unsigned int r;
    asm("mul.hi.u32 %0, %1, %2;" : "=r"(r) : "r"(a), "r"(m));
    return r;
}

// 20-round threefry-2x32, key (0, 42); x1 arrives pre-injected (+42 folded
// by caller). Returns x0 ^ x1 (JAX partitionable fold).
// 4 rounds (the three r=13 and the first r=17) use fma-pipe rotates.
__device__ __forceinline__ unsigned int tf20_xor(unsigned int x1,
                                                 unsigned int one,
                                                 unsigned int m13,
                                                 unsigned int m17) {
    const unsigned int K1 = 42u;
    const unsigned int K2 = 0x1BD11BDAu ^ 42u;  // 0x1BD11BF0
    unsigned int x0, lo, hi;
#define TFR_A(r) { x0 = madd(x1, x0, one); x1 = __funnelshift_l(x1, x1, (r)) ^ x0; }
#define TFR_F(m) { x0 = madd(x1, x0, one); lo = mullo(x1, m); hi = mulhi_(x1, m); \
                   x1 = (lo | hi) ^ x0; }
    // group 1 (x0 starts at 0, so round-1 add is just a copy)
    x0 = x1;
    lo = mullo(x1, m13); hi = mulhi_(x1, m13); x1 = (lo | hi) ^ x0;   // r13, fma
    TFR_A(15) TFR_A(26) TFR_A(6)
    x0 = madd(x0, K1, one);  x1 = madd(x1, K2 + 1u, one);
    // group 2
    TFR_F(m17)                                                        // r17, fma
    TFR_A(29) TFR_A(16) TFR_A(24)
    x0 = madd(x0, K2, one);  x1 = madd(x1, 2u, one);
    // group 3
    TFR_F(m13)                                                        // r13, fma
    TFR_A(15) TFR_A(26) TFR_A(6)
    /* x0 += 0 elided */     x1 = madd(x1, K1 + 3u, one);
    // group 4
    TFR_A(17) TFR_A(29) TFR_A(16) TFR_A(24)
    x0 = madd(x0, K1, one);  x1 = madd(x1, K2 + 4u, one);
    // group 5
    TFR_F(m13)                                                        // r13, fma
    TFR_A(15) TFR_A(26) TFR_A(6)
    x0 = madd(x0, K2, one);  x1 = madd(x1, 5u, one);
#undef TFR_A
#undef TFR_F
    return x0 ^ x1;
}

// One warp per output element (b, o). 8 warps/block share batch row b.
// lane handles 8 float4 chunks (32 samples): i = (k*32 + lane)*4 + c.
__global__ void __launch_bounds__(256)
synapse_kernel(const float* __restrict__ input,
               const float* __restrict__ bias,
               float* __restrict__ out) {
    const int warp = threadIdx.x >> 5;
    const int lane = threadIdx.x & 31;
    const int b = blockIdx.x >> 7;                    // 0..127
    const int o = ((blockIdx.x & 127) << 3) + warp;   // 0..1023

    // memory-opaque constants (ptxas cannot const-fold through memory)
    const unsigned int one = g_rc[0];
    const unsigned int m13 = g_rc[1];
    const unsigned int m17 = g_rc[2];
    const unsigned int m23 = g_rc[3];

    const float bo = bias[o];

    const float4* __restrict__ inrow =
        reinterpret_cast<const float4*>(input + b * IN_DIM);
    const float4* __restrict__ srow =
        reinterpret_cast<const float4*>(g_s23 + o * IN_DIM);

    // x1 init = j + 42, with j = (b*OUT+o)*1024 + lane*4 + k*128 + c
    const unsigned int jtl =
        (((unsigned int)(b * OUT_DIM + o)) << 10) + ((unsigned int)lane << 2) + 42u;

    int cnt = 0;
#pragma unroll
    for (int k = 0; k < 8; ++k) {
        const int v = (k << 5) + lane;      // float4 index within row, 0..255
        const float4 s4 = srow[v];
        const float4 x4 = inrow[v];
        const unsigned int jk = jtl + ((unsigned int)k << 7);

        {
            float p23 = x4.x * s4.x;                     // = clip(x*s,0,1)*2^23 exactly
            unsigned int y = tf20_xor(jk + 0u, one, m13, m17);
            float kf = __uint2float_rn(mulhi_(y, m23));  // (y>>9) exact, < 2^23
            cnt += (kf < p23);                           // == (u < p) exactly
        }
        {
            float p23 = x4.y * s4.y;
            unsigned int y = tf20_xor(jk + 1u, one, m13, m17);
            float kf = __uint2float_rn(mulhi_(y, m23));
            cnt += (kf < p23);
        }
        {
            float p23 = x4.z * s4.z;
            unsigned int y = tf20_xor(jk + 2u, one, m13, m17);
            float kf = __uint2float_rn(mulhi_(y, m23));
            cnt += (kf < p23);
        }
        {
            float p23 = x4.w * s4.w;
            unsigned int y = tf20_xor(jk + 3u, one, m13, m17);
            float kf = __uint2float_rn(mulhi_(y, m23));
            cnt += (kf < p23);
        }
    }

    // warp-level sum of the 32 partial counts
#pragma unroll
    for (int off = 16; off; off >>= 1)
        cnt += __shfl_xor_sync(0xffffffffu, cnt, off);

    if (lane == 0)
        out[b * OUT_DIM + o] = (float)cnt + bo;
}

extern "C" void kernel_launch(void* const* d_in, const int* in_sizes, int n_in,
                              void* d_out, int out_size) {
    const float* input  = (const float*)d_in[0];
    const float* weight = (const float*)d_in[1];
    const float* bias   = (const float*)d_in[2];
    const float* x0     = (const float*)d_in[3];
    const float* dx     = (const float*)d_in[4];
    const float* a      = (const float*)d_in[5];
    const float* d      = (const float*)d_in[6];
    float* out = (float*)d_out;

    prep_kernel<<<(OUT_DIM * IN_DIM) / 256, 256>>>(weight, x0, dx, a, d);
    synapse_kernel<<<B_DIM * (OUT_DIM / 8), 256>>>(input, bias, out);
}

// round 16
// speedup vs baseline: 1.0179x; 1.0179x over previous
#include <cuda_runtime.h>
#include <math.h>

// Problem: B=128, OUT=1024, IN=1024
// d_in: 0=input(128*1024) 1=weight(1024*1024) 2=bias(1024) 3=x0 4=dx 5=a 6=d
// out: (128,1024) float32
//
// res collapses exactly to Yb + bias (bit-exact; rel_err == 0.0 R3/R5/R8).
//
// R9: R8 post-mortem showed latency-bound (issue 0.56 vs pipe-cap 0.99).
//  - REVERT mul-based rotates (cost +4 ops + cross-pipe hops) -> SHF.
//  - KEEP IMAD adds via memory-opaque `one` (free pipe rebalance,
//    f_alu 0.75 -> ~0.56, raising the issue cap 0.67 -> ~0.89).
//  - UNLOCK ILP: __launch_bounds__(256, 2) -> reg budget 128/thread so
//    ptxas keeps ~2x more independent threefry chains live (R8 had 32 regs,
//    too few chains to cover the ~9cyc/round serial latency).

#define B_DIM   128
#define OUT_DIM 1024
#define IN_DIM  1024

// Batch-independent synapse gain, pre-scaled: s23 = 2^23 * (d + a*sigmoid(dx*(w-x0))).
__device__ float g_s23[OUT_DIM * IN_DIM];
// Runtime-written opacity constants: {1, 1<<23}.
__device__ unsigned int g_rc[2];

__global__ void prep_kernel(const float* __restrict__ w,
                            const float* __restrict__ x0,
                            const float* __restrict__ dx,
                            const float* __restrict__ a,
                            const float* __restrict__ d) {
    int idx = blockIdx.x * blockDim.x + threadIdx.x;  // exactly 1M threads
    if (idx == 0) {
        g_rc[0] = 1u;
        g_rc[1] = 1u << 23;
    }
    float z = dx[idx] * (w[idx] - x0[idx]);
    float e = expf(-fabsf(z));
    float t = 1.0f / (1.0f + e);
    float sig = (z >= 0.0f) ? t : e * t;
    g_s23[idx] = (d[idx] + a[idx] * sig) * 8388608.0f;  // * 2^23, exact scale
}

// a + b on the fma pipe: IMAD(a, one, b); `one` is memory-opaque so ptxas
// cannot strength-reduce back to IADD3.
__device__ __forceinline__ unsigned int madd(unsigned int a, unsigned int b,
                                             unsigned int one) {
    unsigned int r;
    asm("mad.lo.u32 %0, %1, %2, %3;" : "=r"(r) : "r"(a), "r"(one), "r"(b));
    return r;
}
__device__ __forceinline__ unsigned int mulhi_(unsigned int a, unsigned int m) {
    unsigned int r;
    asm("mul.hi.u32 %0, %1, %2;" : "=r"(r) : "r"(a), "r"(m));
    return r;
}

// 20-round threefry-2x32, key (0, 42); x1 arrives pre-injected (+42 folded
// by caller). Returns x0 ^ x1 (JAX partitionable fold).
// Rotates on alu (SHF), adds on fma (IMAD).
__device__ __forceinline__ unsigned int tf20_xor(unsigned int x1,
                                                 unsigned int one) {
    const unsigned int K1 = 42u;
    const unsigned int K2 = 0x1BD11BDAu ^ 42u;  // 0x1BD11BF0
    unsigned int x0;
#define TFR(r) { x0 = madd(x1, x0, one); x1 = __funnelshift_l(x1, x1, (r)) ^ x0; }
    // group 1 (x0 starts at 0, so round-1 add is just a copy)
    x0 = x1;
    x1 = __funnelshift_l(x1, x1, 13) ^ x0;
    TFR(15) TFR(26) TFR(6)
    x0 = madd(x0, K1, one);  x1 = madd(x1, K2 + 1u, one);
    TFR(17) TFR(29) TFR(16) TFR(24)
    x0 = madd(x0, K2, one);  x1 = madd(x1, 2u, one);
    TFR(13) TFR(15) TFR(26) TFR(6)
    /* x0 += 0 elided */     x1 = madd(x1, K1 + 3u, one);
    TFR(17) TFR(29) TFR(16) TFR(24)
    x0 = madd(x0, K1, one);  x1 = madd(x1, K2 + 4u, one);
    TFR(13) TFR(15) TFR(26) TFR(6)
    x0 = madd(x0, K2, one);  x1 = madd(x1, 5u, one);
#undef TFR
    return x0 ^ x1;
}

// One warp per output element (b, o). 8 warps/block share batch row b.
// lane handles 8 float4 chunks (32 samples): i = (k*32 + lane)*4 + c.
// minBlocks=2 -> reg budget 128: lets ptxas keep many chains in flight.
__global__ void __launch_bounds__(256, 2)
synapse_kernel(const float* __restrict__ input,
               const float* __restrict__ bias,
               float* __restrict__ out) {
    const int warp = threadIdx.x >> 5;
    const int lane = threadIdx.x & 31;
    const int b = blockIdx.x >> 7;                    // 0..127
    const int o = ((blockIdx.x & 127) << 3) + warp;   // 0..1023

    // memory-opaque constants (ptxas cannot const-fold through memory)
    const unsigned int one = g_rc[0];
    const unsigned int m23 = g_rc[1];

    const float bo = bias[o];

    const float4* __restrict__ inrow =
        reinterpret_cast<const float4*>(input + b * IN_DIM);
    const float4* __restrict__ srow =
        reinterpret_cast<const float4*>(g_s23 + o * IN_DIM);

    // x1 init = j + 42, with j = (b*OUT+o)*1024 + lane*4 + k*128 + c
    const unsigned int jtl =
        (((unsigned int)(b * OUT_DIM + o)) << 10) + ((unsigned int)lane << 2) + 42u;

    int cnt = 0;
#pragma unroll
    for (int k = 0; k < 8; ++k) {
        const int v = (k << 5) + lane;      // float4 index within row, 0..255
        const float4 s4 = srow[v];
        const float4 x4 = inrow[v];
        const unsigned int jk = jtl + ((unsigned int)k << 7);

        {
            float p23 = x4.x * s4.x;                     // = clip(x*s,0,1)*2^23 exactly
            unsigned int y = tf20_xor(jk + 0u, one);
            float kf = __uint2float_rn(mulhi_(y, m23));  // (y>>9) exact, < 2^23
            cnt += (kf < p23);                           // == (u < p) exactly
        }
        {
            float p23 = x4.y * s4.y;
            unsigned int y = tf20_xor(jk + 1u, one);
            float kf = __uint2float_rn(mulhi_(y, m23));
            cnt += (kf < p23);
        }
        {
            float p23 = x4.z * s4.z;
            unsigned int y = tf20_xor(jk + 2u, one);
            float kf = __uint2float_rn(mulhi_(y, m23));
            cnt += (kf < p23);
        }
        {
            float p23 = x4.w * s4.w;
            unsigned int y = tf20_xor(jk + 3u, one);
            float kf = __uint2float_rn(mulhi_(y, m23));
            cnt += (kf < p23);
        }
    }

    // warp-level sum of the 32 partial counts
#pragma unroll
    for (int off = 16; off; off >>= 1)
        cnt += __shfl_xor_sync(0xffffffffu, cnt, off);

    if (lane == 0)
        out[b * OUT_DIM + o] = (float)cnt + bo;
}

extern "C" void kernel_launch(void* const* d_in, const int* in_sizes, int n_in,
                              void* d_out, int out_size) {
    const float* input  = (const float*)d_in[0];
    const float* weight = (const float*)d_in[1];
    const float* bias   = (const float*)d_in[2];
    const float* x0     = (const float*)d_in[3];
    const float* dx     = (const float*)d_in[4];
    const float* a      = (const float*)d_in[5];
    const float* d      = (const float*)d_in[6];
    float* out = (float*)d_out;

    prep_kernel<<<(OUT_DIM * IN_DIM) / 256, 256>>>(weight, x0, dx, a, d);
    synapse_kernel<<<B_DIM * (OUT_DIM / 8), 256>>>(input, bias, out);
}